// round 10
// baseline (speedup 1.0000x reference)
#include <cuda_runtime.h>
#include <cuda_fp16.h>
#include <math.h>

// SigmoidGatedCRFLoss — symmetric-pair halved, fp16-packed smem (16B/q), fp32 math,
// compile-time specialized dy-halves.
//
// loss = [ Σ_{unordered {p,q}} w(p,q)·(P_p B_q + Q_p A_q + P_q B_p + Q_q A_p) ] / max(Σ md, 1)
//   P = md·s, Q = md·(1-s), A = ms·s, B = ms·(1-s), s = sigmoid(y)
//   w = G9(Δ)·(e + 1/9),  G9 = 0.9·exp(-(dx²+dy²)/72)  (0 at center)
//   e = 2^(-Σ du²), u = rgb·sqrt(50·log2 e)  == exp(-50·|Δrgb|²)
// Pixel p claims q ∈ {dy>0} ∪ {dy=0, dx>0} (60 of 121 taps). OOB q -> zero record
// -> whole pair term vanishes (== unfold zero-padding of binarized masks).

#define RAD    5
#define BX     16
#define BY     8
#define TW     32           // 2 px / thread
#define TH     8
#define HW_    42           // TW + 2*RAD
#define HALFW  21
#define HROWS  10           // TH + 3 - 1
#define NT     128

#define RGB_SCALE 8.4932178f   // sqrt(50 * log2(e))

__device__ double   g_num;
__device__ double   g_den;
__device__ unsigned g_ticket;

__device__ __forceinline__ float fast_ex2(float v) {
    float r;
    asm("ex2.approx.f32 %0, %1;" : "=f"(r) : "f"(v));
    return r;
}

// One q record = 16 bytes: (r,g) (b,0) (A,B) (P,Q) as 4x half2.
// One tap = 1 LDS.128, fp32 distance math, HFMA2 accumulate.
template<int JSTART>
__device__ __forceinline__ void do_row(
    const uint4* __restrict__ ev, const uint4* __restrict__ od,
    const float* __restrict__ grow,           // 12 floats: G(j-5, dyy); px1 uses grow[j-1]
    float c0r, float c0g, float c0b,
    float c1r, float c1g, float c1b,
    float& SA0, float& SB0, float& SP0, float& SQ0,
    float& SA1, float& SB1, float& SP1, float& SQ1)
{
    float g[12];
    ((float4*)g)[0] = *(const float4*)&grow[0];
    ((float4*)g)[1] = *(const float4*)&grow[4];
    ((float4*)g)[2] = *(const float4*)&grow[8];

    const __half2 Z2 = __float2half2_rn(0.0f);
    __half2 ab0 = Z2, pq0 = Z2, ab1 = Z2, pq1 = Z2;

    #pragma unroll
    for (int j = JSTART; j < 12; j++) {
        uint4 u = (j & 1) ? od[(j - 1) >> 1] : ev[j >> 1];
        __half2 hrg = *(__half2*)&u.x;
        __half2 hb2 = *(__half2*)&u.y;
        __half2 hab = *(__half2*)&u.z;
        __half2 hpq = *(__half2*)&u.w;
        float qr = __low2float(hrg);
        float qg = __high2float(hrg);
        float qb = __low2float(hb2);

        if (j < 11) {   // pixel0: dx = j-5
            float dr = qr - c0r, dg = qg - c0g, db = qb - c0b;
            float d2n = fmaf(dr, -dr, fmaf(dg, -dg, db * (-db)));
            float w = (fast_ex2(d2n) + 0.11111111f) * g[j];
            __half2 w2 = __float2half2_rn(w);
            ab0 = __hfma2(w2, hab, ab0);
            pq0 = __hfma2(w2, hpq, pq0);
        }
        if (j > 0) {    // pixel1: dx = j-6 -> weight grow[j-1]
            float dr = qr - c1r, dg = qg - c1g, db = qb - c1b;
            float d2n = fmaf(dr, -dr, fmaf(dg, -dg, db * (-db)));
            float w = (fast_ex2(d2n) + 0.11111111f) * g[j - 1];
            __half2 w2 = __float2half2_rn(w);
            ab1 = __hfma2(w2, hab, ab1);
            pq1 = __hfma2(w2, hpq, pq1);
        }
    }
    float2 f;
    f = __half22float2(ab0); SA0 += f.x; SB0 += f.y;
    f = __half22float2(pq0); SP0 += f.x; SQ0 += f.y;
    f = __half22float2(ab1); SA1 += f.x; SB1 += f.y;
    f = __half22float2(pq1); SP1 += f.x; SQ1 += f.y;
}

__global__ __launch_bounds__(NT, 8) void crf_loss_kernel(
    const float* __restrict__ x,      // [N,3,H,W]
    const float* __restrict__ y,      // [N,H,W]
    const float* __restrict__ msrc,   // [N,1,H,W]
    const float* __restrict__ mdst,   // [N,1,H,W]
    float* __restrict__ out,
    int H, int W, unsigned nblocks)
{
    // even/odd column split: unit-stride lane addressing, conflict-free LDS.128
    __shared__ uint4 sEv[HROWS][HALFW];
    __shared__ uint4 sOd[HROWS][HALFW];
    __shared__ __align__(16) float sG[6][12];   // G(j-5, dyy); sG[0][5] = 0 (self pair)
    __shared__ float red[8];

    const int zz    = blockIdx.z;
    const int n     = zz >> 1;
    const int half  = zz & 1;
    const int rbase = half ? 3 : 0;
    const int tx0   = blockIdx.x * TW;
    const int ty0   = blockIdx.y * TH;
    const int cx    = threadIdx.x;     // 0..15
    const int cy    = threadIdx.y;     // 0..7
    const int tid   = cy * BX + cx;
    const int HWp   = H * W;

    const float* __restrict__ xr = x + (size_t)n * 3 * HWp;
    const float* __restrict__ xg = xr + HWp;
    const float* __restrict__ xb = xr + 2 * HWp;
    const float* __restrict__ yp = y    + (size_t)n * HWp;
    const float* __restrict__ mp = msrc + (size_t)n * HWp;
    const float* __restrict__ dp = mdst + (size_t)n * HWp;

    // Shared gaussian table; dx = j-5 in [-5,6]; j=11 (dx=6) only read by px1 (as g[10]).
    for (int i = tid; i < 6 * 12; i += NT) {
        int dyy = i / 12, j = i % 12;
        int dx = j - 5;
        float g = 0.f;
        if (dx <= 5 && !(dyy == 0 && dx == 0))   // zero self pair (center exclusion)
            g = 0.9f * __expf(-(float)(dx * dx + dyy * dyy) * (1.0f / 72.0f));
        sG[dyy][j] = g;
    }

    // Halo fill: rows gy = ty0 + rbase + ly. OOB -> zero record.
    for (int i = tid; i < HW_ * HROWS; i += NT) {
        int ly = i / HW_;
        int lx = i - ly * HW_;
        int gy = ty0 + rbase + ly;
        int gx = tx0 + lx - RAD;
        float r = 0.f, g = 0.f, b = 0.f, A = 0.f, B = 0.f, P = 0.f, Q = 0.f;
        if (gx >= 0 && gx < W && gy >= 0 && gy < H) {
            int idx = gy * W + gx;
            float ms = mp[idx];
            if (isnan(ms) || ms < 1.0f) ms = 0.0f;   // binarize, keep value if >=1
            float md = dp[idx];
            if (isnan(md) || md < 1.0f) md = 0.0f;
            float s = 1.0f / (1.0f + __expf(-yp[idx]));
            r = xr[idx] * RGB_SCALE;
            g = xg[idx] * RGB_SCALE;
            b = xb[idx] * RGB_SCALE;
            A = ms * s;  B = ms - A;
            P = md * s;  Q = md - P;
        }
        __half2 hrg = __floats2half2_rn(r, g);
        __half2 hb2 = __floats2half2_rn(b, 0.f);
        __half2 hab = __floats2half2_rn(A, B);
        __half2 hpq = __floats2half2_rn(P, Q);
        uint4 u;
        u.x = *(unsigned*)&hrg;
        u.y = *(unsigned*)&hb2;
        u.z = *(unsigned*)&hab;
        u.w = *(unsigned*)&hpq;
        int h = lx >> 1;
        if (lx & 1) sOd[ly][h] = u;
        else        sEv[ly][h] = u;
    }
    __syncthreads();

    const int px0 = tx0 + 2 * cx;
    const int py  = ty0 + cy;

    // Centers from gmem, quantized through the SAME fp16 rounding as the halo.
    float c0r, c0g, c0b, c1r, c1g, c1b;
    {
        int i0 = py * W + px0;
        c0r = __half2float(__float2half_rn(xr[i0] * RGB_SCALE));
        c0g = __half2float(__float2half_rn(xg[i0] * RGB_SCALE));
        c0b = __half2float(__float2half_rn(xb[i0] * RGB_SCALE));
        c1r = __half2float(__float2half_rn(xr[i0 + 1] * RGB_SCALE));
        c1g = __half2float(__float2half_rn(xg[i0 + 1] * RGB_SCALE));
        c1b = __half2float(__float2half_rn(xb[i0 + 1] * RGB_SCALE));
    }

    float SA0 = 0.f, SB0 = 0.f, SP0 = 0.f, SQ0 = 0.f;
    float SA1 = 0.f, SB1 = 0.f, SP1 = 0.f, SQ1 = 0.f;

    #define ROWARGS(T) &sEv[cy + (T)][cx], &sOd[cy + (T)][cx]
    #define ACCARGS c0r, c0g, c0b, c1r, c1g, c1b, \
                    SA0, SB0, SP0, SQ0, SA1, SB1, SP1, SQ1
    if (half == 0) {            // dyy = 0,1,2 ; dy0 row claims only dx>0 -> j>=6
        do_row<6>(ROWARGS(0), sG[0], ACCARGS);
        do_row<0>(ROWARGS(1), sG[1], ACCARGS);
        do_row<0>(ROWARGS(2), sG[2], ACCARGS);
    } else {                    // dyy = 3,4,5
        do_row<0>(ROWARGS(0), sG[3], ACCARGS);
        do_row<0>(ROWARGS(1), sG[4], ACCARGS);
        do_row<0>(ROWARGS(2), sG[5], ACCARGS);
    }
    #undef ROWARGS
    #undef ACCARGS

    // Center combine: num_p = P_p·SB + Q_p·SA + B_p·SP + A_p·SQ
    float num = 0.f, den = 0.f;
    {
        int i0 = py * W + px0;
        {
            float ms = mp[i0];
            if (isnan(ms) || ms < 1.0f) ms = 0.0f;
            float md = dp[i0];
            if (isnan(md) || md < 1.0f) md = 0.0f;
            float s = 1.0f / (1.0f + __expf(-yp[i0]));
            float A = ms * s, B = ms - A, P = md * s, Q = md - P;
            num += P * SB0 + Q * SA0 + B * SP0 + A * SQ0;
            if (half == 0) den += md;            // denominator counted once
        }
        {
            float ms = mp[i0 + 1];
            if (isnan(ms) || ms < 1.0f) ms = 0.0f;
            float md = dp[i0 + 1];
            if (isnan(md) || md < 1.0f) md = 0.0f;
            float s = 1.0f / (1.0f + __expf(-yp[i0 + 1]));
            float A = ms * s, B = ms - A, P = md * s, Q = md - P;
            num += P * SB1 + Q * SA1 + B * SP1 + A * SQ1;
            if (half == 0) den += md;
        }
    }

    // Block reduction
    #pragma unroll
    for (int off = 16; off > 0; off >>= 1) {
        num += __shfl_down_sync(0xffffffffu, num, off);
        den += __shfl_down_sync(0xffffffffu, den, off);
    }
    int wid = tid >> 5, lid = tid & 31;
    if (lid == 0) { red[wid] = num; red[4 + wid] = den; }
    __syncthreads();

    if (tid == 0) {
        float ns = red[0] + red[1] + red[2] + red[3];
        float ds = red[4] + red[5] + red[6] + red[7];
        atomicAdd(&g_num, (double)ns);
        atomicAdd(&g_den, (double)ds);
        __threadfence();
        unsigned old = atomicAdd(&g_ticket, 1u);
        if (old == nblocks - 1u) {               // last block finalizes + resets
            double nn = g_num;
            double dd = g_den;
            if (dd < 1.0) dd = 1.0;
            out[0] = (float)(nn / dd);
            g_num = 0.0;
            g_den = 0.0;
            g_ticket = 0u;
        }
    }
}

extern "C" void kernel_launch(void* const* d_in, const int* in_sizes, int n_in,
                              void* d_out, int out_size) {
    const float* x    = (const float*)d_in[0];
    const float* y    = (const float*)d_in[1];
    const float* msrc = (const float*)d_in[2];
    const float* mdst = (const float*)d_in[3];
    float* out = (float*)d_out;

    const int H = 256, W = 256;
    const int N = in_sizes[1] / (H * W);

    dim3 block(BX, BY, 1);
    dim3 grid((W + TW - 1) / TW, (H + TH - 1) / TH, 2 * N);  // dy-halves of claimed set
    unsigned nblocks = grid.x * grid.y * grid.z;
    crf_loss_kernel<<<grid, block>>>(x, y, msrc, mdst, out, H, W, nblocks);
}

// round 11
// speedup vs baseline: 1.0194x; 1.0194x over previous
#include <cuda_runtime.h>
#include <cuda_fp16.h>
#include <math.h>

// SigmoidGatedCRFLoss — symmetric-pair halved, fp16-packed smem records, fp32 tap math,
// register-lean (table in smem, persistent half2 accumulators) for 10-block residency.
//
// loss = [ Σ_{unordered {p,q}} w(p,q)·(P_p B_q + Q_p A_q + P_q B_p + A_p·? ...) ] / max(Σ md, 1)
//   P = md·s, Q = md·(1-s), A = ms·s, B = ms·(1-s), s = sigmoid(y)
//   w = G9·(e + 1/9) = fmaf(e, G9, G9/9),  G9 = 0.9·exp(-(dx²+dy²)/72) (0 at center)
//   e = 2^(-Σ du²), u = rgb·sqrt(50·log2 e)  == exp(-50·|Δrgb|²)
// Pixel p claims q ∈ {dy>0} ∪ {dy=0, dx>0} (60 of 121). OOB q -> zero record ->
// pair term vanishes (== unfold zero-padding of binarized masks).

#define RAD    5
#define BX     16
#define BY     8
#define TW     32           // 2 px / thread
#define TH     8
#define HW_    42           // TW + 2*RAD
#define HALFW  21
#define HROWS  10           // TH + 3 - 1
#define NT     128

#define RGB_SCALE 8.4932178f   // sqrt(50 * log2(e))

__device__ double   g_num;
__device__ double   g_den;
__device__ unsigned g_ticket;

__device__ __forceinline__ float fast_ex2(float v) {
    float r;
    asm("ex2.approx.f32 %0, %1;" : "=f"(r) : "f"(v));
    return r;
}

// One q record = 16B: (r,g)(b,·)(A,B)(P,Q) as 4x half2. 1 LDS.128 per j serves both pixels.
// Weight table row entry (16B): (g0, g0/9, g1, g1/9); g0 = G(j-5,dyy) for px0,
// g1 = G(j-6,dyy) for px1. Zero-padded for invalid dx and the self-pair.
template<int JSTART>
__device__ __forceinline__ void do_row(
    const uint4* __restrict__ ev, const uint4* __restrict__ od,
    const float4* __restrict__ gt,
    float c0r, float c0g, float c0b,
    float c1r, float c1g, float c1b,
    __half2& ab0, __half2& pq0, __half2& ab1, __half2& pq1)
{
    #pragma unroll
    for (int j = JSTART; j < 12; j++) {
        uint4 u = (j & 1) ? od[(j - 1) >> 1] : ev[j >> 1];
        __half2 hrg = *(__half2*)&u.x;
        __half2 hb2 = *(__half2*)&u.y;
        __half2 hab = *(__half2*)&u.z;
        __half2 hpq = *(__half2*)&u.w;
        float qr = __low2float(hrg);
        float qg = __high2float(hrg);
        float qb = __low2float(hb2);
        float4 gq = gt[j];                       // broadcast LDS.128

        if (j < 11) {   // pixel0: dx = j-5
            float dr = qr - c0r, dg = qg - c0g, db = qb - c0b;
            float d2n = fmaf(dr, -dr, fmaf(dg, -dg, db * (-db)));
            float w = fmaf(fast_ex2(d2n), gq.x, gq.y);
            __half2 w2 = __float2half2_rn(w);
            ab0 = __hfma2(w2, hab, ab0);
            pq0 = __hfma2(w2, hpq, pq0);
        }
        if (j > 0) {    // pixel1: dx = j-6
            float dr = qr - c1r, dg = qg - c1g, db = qb - c1b;
            float d2n = fmaf(dr, -dr, fmaf(dg, -dg, db * (-db)));
            float w = fmaf(fast_ex2(d2n), gq.z, gq.w);
            __half2 w2 = __float2half2_rn(w);
            ab1 = __hfma2(w2, hab, ab1);
            pq1 = __hfma2(w2, hpq, pq1);
        }
    }
}

__global__ __launch_bounds__(NT, 10) void crf_loss_kernel(
    const float* __restrict__ x,      // [N,3,H,W]
    const float* __restrict__ y,      // [N,H,W]
    const float* __restrict__ msrc,   // [N,1,H,W]
    const float* __restrict__ mdst,   // [N,1,H,W]
    float* __restrict__ out,
    int H, int W, unsigned nblocks)
{
    // even/odd column split: unit-stride lane addressing, conflict-free LDS.128
    __shared__ uint4  sEv[HROWS][HALFW];
    __shared__ uint4  sOd[HROWS][HALFW];
    __shared__ float4 sGP[6][12];        // (g0, g0/9, g1, g1/9) per (dyy, j)
    __shared__ float  red[8];

    const int zz    = blockIdx.z;
    const int n     = zz >> 1;
    const int half  = zz & 1;
    const int rbase = half ? 3 : 0;
    const int tx0   = blockIdx.x * TW;
    const int ty0   = blockIdx.y * TH;
    const int cx    = threadIdx.x;     // 0..15
    const int cy    = threadIdx.y;     // 0..7
    const int tid   = cy * BX + cx;
    const int HWp   = H * W;

    const float* __restrict__ xr = x + (size_t)n * 3 * HWp;
    const float* __restrict__ xg = xr + HWp;
    const float* __restrict__ xb = xr + 2 * HWp;
    const float* __restrict__ yp = y    + (size_t)n * HWp;
    const float* __restrict__ mp = msrc + (size_t)n * HWp;
    const float* __restrict__ dp = mdst + (size_t)n * HWp;

    // Weight table. px0: dx0=j-5 valid in [-5,5]; px1: dx1=j-6 valid in [-5,5].
    // Self-pair (dyy==0, dx==0) zeroed => kernels[:,:,center]=0 for both descriptors.
    for (int i = tid; i < 6 * 12; i += NT) {
        int dyy = i / 12, j = i % 12;
        float g0 = 0.f, g1 = 0.f;
        int dx0 = j - 5;
        if (dx0 >= -5 && dx0 <= 5 && !(dyy == 0 && dx0 == 0))
            g0 = 0.9f * __expf(-(float)(dx0 * dx0 + dyy * dyy) * (1.0f / 72.0f));
        int dx1 = j - 6;
        if (dx1 >= -5 && dx1 <= 5 && !(dyy == 0 && dx1 == 0))
            g1 = 0.9f * __expf(-(float)(dx1 * dx1 + dyy * dyy) * (1.0f / 72.0f));
        sGP[dyy][j] = make_float4(g0, g0 * (1.0f / 9.0f), g1, g1 * (1.0f / 9.0f));
    }

    // Halo fill: rows gy = ty0 + rbase + ly. OOB -> zero record.
    for (int i = tid; i < HW_ * HROWS; i += NT) {
        int ly = i / HW_;
        int lx = i - ly * HW_;
        int gy = ty0 + rbase + ly;
        int gx = tx0 + lx - RAD;
        float r = 0.f, g = 0.f, b = 0.f, A = 0.f, B = 0.f, P = 0.f, Q = 0.f;
        if (gx >= 0 && gx < W && gy >= 0 && gy < H) {
            int idx = gy * W + gx;
            float ms = mp[idx];
            if (isnan(ms) || ms < 1.0f) ms = 0.0f;   // binarize, keep value if >=1
            float md = dp[idx];
            if (isnan(md) || md < 1.0f) md = 0.0f;
            float s = 1.0f / (1.0f + __expf(-yp[idx]));
            r = xr[idx] * RGB_SCALE;
            g = xg[idx] * RGB_SCALE;
            b = xb[idx] * RGB_SCALE;
            A = ms * s;  B = ms - A;
            P = md * s;  Q = md - P;
        }
        __half2 hrg = __floats2half2_rn(r, g);
        __half2 hb2 = __floats2half2_rn(b, 0.f);
        __half2 hab = __floats2half2_rn(A, B);
        __half2 hpq = __floats2half2_rn(P, Q);
        uint4 u;
        u.x = *(unsigned*)&hrg;
        u.y = *(unsigned*)&hb2;
        u.z = *(unsigned*)&hab;
        u.w = *(unsigned*)&hpq;
        int h = lx >> 1;
        if (lx & 1) sOd[ly][h] = u;
        else        sEv[ly][h] = u;
    }
    __syncthreads();

    const int px0 = tx0 + 2 * cx;
    const int py  = ty0 + cy;

    // Centers from gmem, quantized through the SAME fp16 rounding as the halo.
    float c0r, c0g, c0b, c1r, c1g, c1b;
    {
        int i0 = py * W + px0;
        c0r = __half2float(__float2half_rn(xr[i0] * RGB_SCALE));
        c0g = __half2float(__float2half_rn(xg[i0] * RGB_SCALE));
        c0b = __half2float(__float2half_rn(xb[i0] * RGB_SCALE));
        c1r = __half2float(__float2half_rn(xr[i0 + 1] * RGB_SCALE));
        c1g = __half2float(__float2half_rn(xg[i0 + 1] * RGB_SCALE));
        c1b = __half2float(__float2half_rn(xb[i0 + 1] * RGB_SCALE));
    }

    const __half2 Z2 = __float2half2_rn(0.0f);
    __half2 ab0 = Z2, pq0 = Z2, ab1 = Z2, pq1 = Z2;

    #define ROWARGS(T) &sEv[cy + (T)][cx], &sOd[cy + (T)][cx]
    #define ACCARGS c0r, c0g, c0b, c1r, c1g, c1b, ab0, pq0, ab1, pq1
    if (half == 0) {            // dyy = 0,1,2; dy0 row claims only dx>0 -> j>=6
        do_row<6>(ROWARGS(0), sGP[0], ACCARGS);
        do_row<0>(ROWARGS(1), sGP[1], ACCARGS);
        do_row<0>(ROWARGS(2), sGP[2], ACCARGS);
    } else {                    // dyy = 3,4,5
        do_row<0>(ROWARGS(0), sGP[3], ACCARGS);
        do_row<0>(ROWARGS(1), sGP[4], ACCARGS);
        do_row<0>(ROWARGS(2), sGP[5], ACCARGS);
    }
    #undef ROWARGS
    #undef ACCARGS

    // Single fp32 spill of the half2 accumulators
    float SA0, SB0, SP0, SQ0, SA1, SB1, SP1, SQ1;
    {
        float2 f;
        f = __half22float2(ab0); SA0 = f.x; SB0 = f.y;
        f = __half22float2(pq0); SP0 = f.x; SQ0 = f.y;
        f = __half22float2(ab1); SA1 = f.x; SB1 = f.y;
        f = __half22float2(pq1); SP1 = f.x; SQ1 = f.y;
    }

    // Center combine: num_p = P_p·SB + Q_p·SA + B_p·SP + A_p·SQ
    float num = 0.f, den = 0.f;
    {
        int i0 = py * W + px0;
        {
            float ms = mp[i0];
            if (isnan(ms) || ms < 1.0f) ms = 0.0f;
            float md = dp[i0];
            if (isnan(md) || md < 1.0f) md = 0.0f;
            float s = 1.0f / (1.0f + __expf(-yp[i0]));
            float A = ms * s, B = ms - A, P = md * s, Q = md - P;
            num += P * SB0 + Q * SA0 + B * SP0 + A * SQ0;
            if (half == 0) den += md;            // denominator counted once
        }
        {
            float ms = mp[i0 + 1];
            if (isnan(ms) || ms < 1.0f) ms = 0.0f;
            float md = dp[i0 + 1];
            if (isnan(md) || md < 1.0f) md = 0.0f;
            float s = 1.0f / (1.0f + __expf(-yp[i0 + 1]));
            float A = ms * s, B = ms - A, P = md * s, Q = md - P;
            num += P * SB1 + Q * SA1 + B * SP1 + A * SQ1;
            if (half == 0) den += md;
        }
    }

    // Block reduction
    #pragma unroll
    for (int off = 16; off > 0; off >>= 1) {
        num += __shfl_down_sync(0xffffffffu, num, off);
        den += __shfl_down_sync(0xffffffffu, den, off);
    }
    int wid = tid >> 5, lid = tid & 31;
    if (lid == 0) { red[wid] = num; red[4 + wid] = den; }
    __syncthreads();

    if (tid == 0) {
        float ns = red[0] + red[1] + red[2] + red[3];
        float ds = red[4] + red[5] + red[6] + red[7];
        atomicAdd(&g_num, (double)ns);
        atomicAdd(&g_den, (double)ds);
        __threadfence();
        unsigned old = atomicAdd(&g_ticket, 1u);
        if (old == nblocks - 1u) {               // last block finalizes + resets
            double nn = g_num;
            double dd = g_den;
            if (dd < 1.0) dd = 1.0;
            out[0] = (float)(nn / dd);
            g_num = 0.0;
            g_den = 0.0;
            g_ticket = 0u;
        }
    }
}

extern "C" void kernel_launch(void* const* d_in, const int* in_sizes, int n_in,
                              void* d_out, int out_size) {
    const float* x    = (const float*)d_in[0];
    const float* y    = (const float*)d_in[1];
    const float* msrc = (const float*)d_in[2];
    const float* mdst = (const float*)d_in[3];
    float* out = (float*)d_out;

    const int H = 256, W = 256;
    const int N = in_sizes[1] / (H * W);

    dim3 block(BX, BY, 1);
    dim3 grid((W + TW - 1) / TW, (H + TH - 1) / TH, 2 * N);  // dy-halves of claimed set
    unsigned nblocks = grid.x * grid.y * grid.z;
    crf_loss_kernel<<<grid, block>>>(x, y, msrc, mdst, out, H, W, nblocks);
}